// round 5
// baseline (speedup 1.0000x reference)
#include <cuda_runtime.h>
#include <cstdint>

// LinearInt4: out[32,11008] = x[32,4096] @ dequant(q[11008,4096]).T
// w[n,k] = (q-8)*s[g,n] + z[g,n],  g = k/128
//
//  k0: transpose x -> g_xT[k][m]
//  k1: split-K GEMM, 43 n-tiles x 16 k-splits, cp.async double-buffered
//      staging of q (coalesced). Dequant: magic-number int->float, EXACT
//      Sterbenz un-bias (q|0x4B000000 as float, minus 2^23+8 == q-8 exactly),
//      then one fma at natural scale. Inner product with packed fma.rn.f32x2.
//      Partials -> g_part[ks][m][n] (deterministic, no atomics)
//  k2: reduce 16 partials -> out

#define M_ROWS 32
#define K_DIM  4096
#define N_DIM  11008
#define NTILE  256      // n per block
#define KTILE  256      // k per block (2 groups)
#define KCHUNK 16       // k per smem stage
#define NSPLIT 16       // K_DIM / KTILE
#define NNT    43       // N_DIM / NTILE
#define GSIZE  128

__device__ float g_xT[K_DIM * M_ROWS];             // [k][m]
__device__ float g_part[NSPLIT * M_ROWS * N_DIM];  // [ks][m][n]

__global__ void transpose_x_kernel(const float* __restrict__ x) {
  int idx = blockIdx.x * blockDim.x + threadIdx.x;
  if (idx < M_ROWS * K_DIM) {
    int m = idx / K_DIM;
    int k = idx % K_DIM;
    g_xT[k * M_ROWS + m] = x[idx];   // coalesced read, scattered 4B write (tiny)
  }
}

__device__ __forceinline__ void cp16(void* smem_dst, const void* gptr) {
  unsigned s = (unsigned)__cvta_generic_to_shared(smem_dst);
  asm volatile("cp.async.cg.shared.global [%0], [%1], 16;\n" :: "r"(s), "l"(gptr));
}

__global__ void __launch_bounds__(128)
int4mm_main_kernel(const int* __restrict__ q, const float* __restrict__ sz) {
  __shared__ float xs[2][KCHUNK][M_ROWS];   // 4 KB
  __shared__ int   qs[2][NTILE][KCHUNK];    // 32 KB

  const int t  = threadIdx.x;               // 0..127
  const int n0 = blockIdx.x * NTILE;
  const int k0 = blockIdx.y * KTILE;
  const int na = n0 + t;                    // this thread's two n-rows
  const int nb = n0 + 128 + t;

  // Per-group scale/zero for both owned n-rows (two groups per KTILE).
  float sa[2], za[2], sb[2], zb[2];
  const int g0 = k0 / GSIZE;
#pragma unroll
  for (int g = 0; g < 2; g++) {
    sa[g] = sz[((size_t)(g0 + g) * N_DIM + na) * 2 + 0];
    za[g] = sz[((size_t)(g0 + g) * N_DIM + na) * 2 + 1];
    sb[g] = sz[((size_t)(g0 + g) * N_DIM + nb) * 2 + 0];
    zb[g] = sz[((size_t)(g0 + g) * N_DIM + nb) * 2 + 1];
  }

  unsigned long long accA[16], accB[16];    // f32x2 pairs: accA[i] = m {2i, 2i+1}
#pragma unroll
  for (int i = 0; i < 16; i++) { accA[i] = 0ull; accB[i] = 0ull; }

  auto stage = [&](int c, int buf) {
    const int kc = k0 + c * KCHUNK;
    // x chunk: contiguous 2 KB of g_xT
    cp16(&xs[buf][0][0] + t * 4, g_xT + (size_t)kc * M_ROWS + t * 4);
    // q chunk: 256 rows x 64 B
#pragma unroll
    for (int i = 0; i < 8; i++) {
      int c2  = t + i * 128;
      int nl  = c2 >> 2;
      int seg = c2 & 3;
      cp16(&qs[buf][nl][seg * 4],
           q + (size_t)(n0 + nl) * K_DIM + kc + seg * 4);
    }
  };

  stage(0, 0);
  asm volatile("cp.async.commit_group;\n" ::: "memory");
  stage(1, 1);
  asm volatile("cp.async.commit_group;\n" ::: "memory");

  const int nchunks = KTILE / KCHUNK;       // 16
  for (int c = 0; c < nchunks; c++) {
    const int buf = c & 1;
    asm volatile("cp.async.wait_group 1;\n" ::: "memory");
    __syncthreads();

    const int g = (c * KCHUNK) / GSIZE;     // 0 or 1
    const float vsa = sa[g], vza = za[g], vsb = sb[g], vzb = zb[g];
    const int4* qaRow = reinterpret_cast<const int4*>(&qs[buf][t][0]);
    const int4* qbRow = reinterpret_cast<const int4*>(&qs[buf][t + 128][0]);

#pragma unroll
    for (int k4 = 0; k4 < KCHUNK / 4; k4++) {
      const int4 qav = qaRow[k4];
      const int4 qbv = qbRow[k4];
      const int qai[4] = {qav.x, qav.y, qav.z, qav.w};
      const int qbi[4] = {qbv.x, qbv.y, qbv.z, qbv.w};
#pragma unroll
      for (int j = 0; j < 4; j++) {
        const int kk = k4 * 4 + j;
        // Exact dequant: float(2^23 + q) - (2^23 + 8) == q - 8 (Sterbenz, exact)
        float qaf = __int_as_float(qai[j] | 0x4B000000) - 8388616.0f;
        float qbf = __int_as_float(qbi[j] | 0x4B000000) - 8388616.0f;
        float wa  = fmaf(qaf, vsa, vza);
        float wb  = fmaf(qbf, vsb, vzb);
        unsigned long long wa2, wb2;
        asm("mov.b64 %0, {%1, %2};" : "=l"(wa2) : "f"(wa), "f"(wa));
        asm("mov.b64 %0, {%1, %2};" : "=l"(wb2) : "f"(wb), "f"(wb));
        const ulonglong2* xv =
            reinterpret_cast<const ulonglong2*>(&xs[buf][kk][0]);
#pragma unroll
        for (int p = 0; p < 8; p++) {
          ulonglong2 x2 = xv[p];            // x[kk][4p..4p+3], broadcast LDS.128
          asm("fma.rn.f32x2 %0, %1, %2, %0;" : "+l"(accA[2*p  ]) : "l"(x2.x), "l"(wa2));
          asm("fma.rn.f32x2 %0, %1, %2, %0;" : "+l"(accA[2*p+1]) : "l"(x2.y), "l"(wa2));
          asm("fma.rn.f32x2 %0, %1, %2, %0;" : "+l"(accB[2*p  ]) : "l"(x2.x), "l"(wb2));
          asm("fma.rn.f32x2 %0, %1, %2, %0;" : "+l"(accB[2*p+1]) : "l"(x2.y), "l"(wb2));
        }
      }
    }

    __syncthreads();
    if (c + 2 < nchunks) stage(c + 2, buf);
    asm volatile("cp.async.commit_group;\n" ::: "memory");
  }

  // Epilogue: scatter partials (coalesced per-m rows across the warp)
  float* part = g_part + (size_t)blockIdx.y * M_ROWS * N_DIM;
#pragma unroll
  for (int i = 0; i < 16; i++) {
    float lo, hi;
    asm("mov.b64 {%0, %1}, %2;" : "=f"(lo), "=f"(hi) : "l"(accA[i]));
    part[(size_t)(2*i    ) * N_DIM + na] = lo;
    part[(size_t)(2*i + 1) * N_DIM + na] = hi;
    asm("mov.b64 {%0, %1}, %2;" : "=f"(lo), "=f"(hi) : "l"(accB[i]));
    part[(size_t)(2*i    ) * N_DIM + nb] = lo;
    part[(size_t)(2*i + 1) * N_DIM + nb] = hi;
  }
}

__global__ void reduce_part_kernel(float* __restrict__ out) {
  int idx = blockIdx.x * blockDim.x + threadIdx.x;
  if (idx < M_ROWS * N_DIM) {
    float s = 0.0f;
#pragma unroll
    for (int i = 0; i < NSPLIT; i++)
      s += g_part[(size_t)i * M_ROWS * N_DIM + idx];
    out[idx] = s;
  }
}

extern "C" void kernel_launch(void* const* d_in, const int* in_sizes, int n_in,
                              void* d_out, int out_size) {
  const float* x  = (const float*)d_in[0];
  const int*   q  = (const int*)d_in[1];
  const float* sz = (const float*)d_in[2];
  float* out = (float*)d_out;

  transpose_x_kernel<<<(M_ROWS * K_DIM + 255) / 256, 256>>>(x);
  dim3 grid(NNT, NSPLIT);
  int4mm_main_kernel<<<grid, 128>>>(q, sz);
  reduce_part_kernel<<<(M_ROWS * N_DIM + 255) / 256, 256>>>(out);
}

// round 7
// speedup vs baseline: 1.6485x; 1.6485x over previous
#include <cuda_runtime.h>
#include <cstdint>

// out[32,11008] = x[32,4096] @ dequant(q[11008,4096]).T
// via mma.sync.m16n8k8 tf32 (base sm_103 target; tcgen05 unavailable).
// w[n,k] = (q-8)*s[g,n] + z[g,n] dequantized in registers, rn-rounded to tf32.
// k-permuted fragments: lane quad c owns actual k {4c..4c+3} of each k16 slice
// in BOTH A and B (sum over k is permutation invariant), so q and x fragment
// loads are single LDG.128s.

#define M_ROWS 32
#define K_DIM  4096
#define N_DIM  11008
#define KSPLIT 8
#define KBLK   (K_DIM / KSPLIT)     // 512 -> 32 k16-steps per block
#define NWARPS 8
#define NTILE  (NWARPS * 16)        // 128 n per block
#define NNT    (N_DIM / NTILE)      // 86

__device__ float g_part[KSPLIT * (size_t)N_DIM * M_ROWS];  // [ks][n][m]
__device__ float g_xf[K_DIM * M_ROWS];                     // [k16][m(32)][kk(16)] tf32 bits

__device__ __forceinline__ uint32_t deq_tf32(int qi, float s, float z) {
  float qf = __int_as_float(qi | 0x4B000000) - 8388616.0f;  // exact q-8 (Sterbenz)
  float wv = fmaf(qf, s, z);
  uint32_t r;
  asm("cvt.rn.tf32.f32 %0, %1;" : "=r"(r) : "f"(wv));
  return r;
}

__device__ __forceinline__ void mma_tf32(float* d, uint32_t a0, uint32_t a1,
                                         uint32_t a2, uint32_t a3,
                                         uint32_t b0, uint32_t b1) {
  asm volatile(
      "mma.sync.aligned.m16n8k8.row.col.f32.tf32.tf32.f32 "
      "{%0,%1,%2,%3}, {%4,%5,%6,%7}, {%8,%9}, {%0,%1,%2,%3};"
      : "+f"(d[0]), "+f"(d[1]), "+f"(d[2]), "+f"(d[3])
      : "r"(a0), "r"(a1), "r"(a2), "r"(a3), "r"(b0), "r"(b1));
}

// x -> tf32-rounded fragment layout [k/16][m][k%16]
__global__ void xprep_kernel(const float* __restrict__ x) {
  int idx = blockIdx.x * blockDim.x + threadIdx.x;
  if (idx >= M_ROWS * K_DIM) return;
  int m = idx >> 12;
  int k = idx & (K_DIM - 1);
  float v = x[idx];
  uint32_t r;
  asm("cvt.rn.tf32.f32 %0, %1;" : "=r"(r) : "f"(v));
  ((uint32_t*)g_xf)[(k >> 4) * (M_ROWS * 16) + m * 16 + (k & 15)] = r;
}

__global__ void __launch_bounds__(256)
int4mm_mma_kernel(const int* __restrict__ q, const float* __restrict__ sz) {
  const int t    = threadIdx.x;
  const int w    = t >> 5;
  const int lane = t & 31;
  const int gp   = lane >> 2;        // 0..7
  const int c    = lane & 3;         // quad lane -> owns k {4c..4c+3}
  const int ks   = blockIdx.y;
  const int n0   = blockIdx.x * NTILE + w * 16;
  const int kb0  = ks * (KBLK / 16); // first k16-step index

  const int rA = n0 + gp;            // A-frag rows (n-dim)
  const int rB = rA + 8;

  float acc[4][4];
#pragma unroll
  for (int i = 0; i < 4; i++)
#pragma unroll
    for (int j = 0; j < 4; j++) acc[i][j] = 0.0f;

  const int4*   qA4 = (const int4*)q + (size_t)rA * (K_DIM / 4);
  const int4*   qB4 = (const int4*)q + (size_t)rB * (K_DIM / 4);
  const float4* xf4 = (const float4*)g_xf;   // idx = kb*128 + m*4 + c
  const float2* szp = (const float2*)sz;     // [g][n] {s,z}

  // prefetch k-step 0
  int4 qa_c = qA4[kb0 * 4 + c];
  int4 qb_c = qB4[kb0 * 4 + c];

  for (int g = 0; g < 4; g++) {
    const int gg = ks * 4 + g;                     // global 128-group
    const float2 vA = szp[(size_t)gg * N_DIM + rA];
    const float2 vB = szp[(size_t)gg * N_DIM + rB];
#pragma unroll
    for (int kk = 0; kk < 8; kk++) {
      const int kstep = g * 8 + kk;
      const int kb    = kb0 + kstep;
      // prefetch next q (wrap to kb0 on last iter; harmless valid read)
      const int ksn = (kstep + 1 < 32) ? (kstep + 1) : 0;
      int4 qa_n = qA4[(kb0 + ksn) * 4 + c];
      int4 qb_n = qB4[(kb0 + ksn) * 4 + c];

      // x fragments for this k16 (L2-resident): xv[mt] = x[8mt+gp][4c..4c+3]
      float4 xv[4];
#pragma unroll
      for (int mt = 0; mt < 4; mt++)
        xv[mt] = xf4[(size_t)kb * 128 + (8 * mt + gp) * 4 + c];

      // dequant 8 weights -> tf32
      uint32_t wA0 = deq_tf32(qa_c.x, vA.x, vA.y);
      uint32_t wA1 = deq_tf32(qa_c.y, vA.x, vA.y);
      uint32_t wA2 = deq_tf32(qa_c.z, vA.x, vA.y);
      uint32_t wA3 = deq_tf32(qa_c.w, vA.x, vA.y);
      uint32_t wB0 = deq_tf32(qb_c.x, vB.x, vB.y);
      uint32_t wB1 = deq_tf32(qb_c.y, vB.x, vB.y);
      uint32_t wB2 = deq_tf32(qb_c.z, vB.x, vB.y);
      uint32_t wB3 = deq_tf32(qb_c.w, vB.x, vB.y);

#pragma unroll
      for (int mt = 0; mt < 4; mt++) {
        // k8 step 0: actual k {4c, 4c+1}
        mma_tf32(acc[mt], wA0, wB0, wA1, wB1,
                 __float_as_uint(xv[mt].x), __float_as_uint(xv[mt].y));
        // k8 step 1: actual k {4c+2, 4c+3}
        mma_tf32(acc[mt], wA2, wB2, wA3, wB3,
                 __float_as_uint(xv[mt].z), __float_as_uint(xv[mt].w));
      }
      qa_c = qa_n;
      qb_c = qb_n;
    }
  }

  // partials: [ks][n][m]; D frag: c0,c1 = (row gp, cols 2c,2c+1), c2,c3 = row gp+8
  float* part = g_part + (size_t)ks * N_DIM * M_ROWS;
#pragma unroll
  for (int mt = 0; mt < 4; mt++) {
    int mcol = 8 * mt + 2 * c;
    *(float2*)&part[(size_t)rA * M_ROWS + mcol] = make_float2(acc[mt][0], acc[mt][1]);
    *(float2*)&part[(size_t)rB * M_ROWS + mcol] = make_float2(acc[mt][2], acc[mt][3]);
  }
}

// sum split-K partials + transpose [n][m] -> out[m][n]
__global__ void reduce_t_kernel(float* __restrict__ out) {
  __shared__ float sm[32][33];
  const int n0 = blockIdx.x * 32;
  const int xx = threadIdx.x, yy = threadIdx.y;
  float s = 0.0f;
  const size_t off = (size_t)(n0 + yy) * M_ROWS + xx;   // coalesced in xx
#pragma unroll
  for (int ks = 0; ks < KSPLIT; ks++)
    s += g_part[(size_t)ks * N_DIM * M_ROWS + off];
  sm[yy][xx] = s;                     // sm[n_local][m]
  __syncthreads();
  out[(size_t)yy * N_DIM + n0 + xx] = sm[xx][yy];   // coalesced in xx
}

extern "C" void kernel_launch(void* const* d_in, const int* in_sizes, int n_in,
                              void* d_out, int out_size) {
  const float* x  = (const float*)d_in[0];
  const int*   q  = (const int*)d_in[1];
  const float* sz = (const float*)d_in[2];
  float* out = (float*)d_out;

  xprep_kernel<<<(M_ROWS * K_DIM + 255) / 256, 256>>>(x);
  dim3 grid(NNT, KSPLIT);
  int4mm_mma_kernel<<<grid, 256>>>(q, sz);
  dim3 rblk(32, 32);
  reduce_t_kernel<<<N_DIM / 32, rblk>>>(out);
}